// round 6
// baseline (speedup 1.0000x reference)
#include <cuda_runtime.h>
#include <math.h>

#define G 2048
#define F 128
#define IN0 144
#define TM 64
#define EPS 1e-5f
#define SA 148
#define SB 132

typedef unsigned long long u64;

// ---------------- scratch ----------------------------------------------------
__device__ __align__(16) float d_hbuf[500000 * 128];
__device__ int   d_off[G + 1];
__device__ __align__(16) float d_xm[G * IN0];
__device__ __align__(16) float d_lam1[G * F];
__device__ __align__(16) float d_hm[G * F];
__device__ __align__(16) float d_lam2[G * F];
__device__ __align__(16) float d_S[2 * F];
__device__ __align__(16) float d_scale[F];
__device__ __align__(16) float d_shift[F];

// ---------------- f32x2 helpers ----------------------------------------------
__device__ __forceinline__ u64 pk2(float v) {
    u64 r; asm("mov.b64 %0,{%1,%1};" : "=l"(r) : "f"(v)); return r;
}
__device__ __forceinline__ void fma2(u64& d, u64 a, u64 b) {
    asm("fma.rn.f32x2 %0,%1,%2,%0;" : "+l"(d) : "l"(a), "l"(b));
}
__device__ __forceinline__ void upk(u64 v, float& lo, float& hi) {
    asm("mov.b64 {%0,%1},%2;" : "=f"(lo), "=f"(hi) : "l"(v));
}

// ---------------- K0: graph offsets ------------------------------------------
__global__ void k_off(const int* __restrict__ batch, int N) {
    int g = blockIdx.x * blockDim.x + threadIdx.x;
    if (g > G) return;
    int lo = 0, hi = N;
    while (lo < hi) { int mid = (lo + hi) >> 1; if (batch[mid] < g) lo = mid + 1; else hi = mid; }
    d_off[g] = lo;
}

// ---------------- K1: xm = segment_mean(x0) ----------------------------------
__global__ void k_xm(const float* __restrict__ x, const float* __restrict__ pers, int N) {
    int g = blockIdx.x;
    int j = threadIdx.x;
    if (j >= IN0) return;
    int s = d_off[g], e = d_off[g + 1];
    float a0 = 0.f, a1 = 0.f, a2 = 0.f, a3 = 0.f;
    if (j < F) {
        const float* p = x + j;
        int n = s;
        for (; n + 3 < e; n += 4) {
            a0 += p[(size_t)n * F];       a1 += p[(size_t)(n + 1) * F];
            a2 += p[(size_t)(n + 2) * F]; a3 += p[(size_t)(n + 3) * F];
        }
        for (; n < e; ++n) a0 += p[(size_t)n * F];
    } else {
        int jj = j - F; int pp = jj >> 1; int c = jj & 1;
        const float* p = pers + (size_t)pp * N * 2 + c;
        int n = s;
        for (; n + 3 < e; n += 4) {
            a0 += p[(size_t)n * 2];       a1 += p[(size_t)(n + 1) * 2];
            a2 += p[(size_t)(n + 2) * 2]; a3 += p[(size_t)(n + 3) * 2];
        }
        for (; n < e; ++n) a0 += p[(size_t)n * 2];
    }
    d_xm[g * IN0 + j] = (a0 + a1 + a2 + a3) / fmaxf((float)(e - s), 1.f);
}

// ---------------- K2: lam1 = xm @ l1w^T --------------------------------------
__global__ void k_lam1(const float* __restrict__ l1w) {
    __shared__ float mr[IN0];
    int g = blockIdx.x, j = threadIdx.x;
    for (int k = j; k < IN0; k += 128) mr[k] = d_xm[g * IN0 + k];
    __syncthreads();
    float acc = 0.f;
    const float* w = l1w + j * IN0;
    #pragma unroll 4
    for (int k = 0; k < IN0; ++k) acc += mr[k] * w[k];
    d_lam1[g * F + j] = acc;
}

// ---------------- K3: h = relu(x0 @ g1w^T + g1b - lam1[batch]) ---------------
// 128 threads, TM=64 rows, full F=128 cols. Thread: 4 rows x 16 cols, f32x2.
__global__ __launch_bounds__(128, 2) void k_gemm1(
        const float* __restrict__ x, const float* __restrict__ pers,
        const int* __restrict__ batch,
        const float* __restrict__ g1w, const float* __restrict__ g1b, int N) {
    extern __shared__ float sm[];
    float* wt = sm;                      // [IN0][F]  wt[k*128+j] = g1w[j*IN0+k]
    float* as = sm + IN0 * F;            // [TM][SA]
    int*   bs = (int*)(as + TM * SA);
    int tid = threadIdx.x;
    int n0 = blockIdx.x * TM;

    for (int idx = tid; idx < IN0 * F; idx += 128) {
        int k = idx >> 7, j = idx & 127;
        wt[idx] = g1w[j * IN0 + k];
    }
    for (int idx = tid; idx < TM * 32; idx += 128) {
        int r = idx >> 5, c4 = idx & 31;
        int n = n0 + r;
        float4 v = (n < N) ? *(const float4*)&x[(size_t)n * F + c4 * 4]
                           : make_float4(0.f, 0.f, 0.f, 0.f);
        *(float4*)&as[r * SA + c4 * 4] = v;
    }
    for (int idx = tid; idx < TM * 16; idx += 128) {
        int r = idx >> 4, jj = idx & 15;
        int n = n0 + r;
        int pp = jj >> 1, c = jj & 1;
        as[r * SA + F + jj] = (n < N) ? pers[(size_t)pp * N * 2 + (size_t)n * 2 + c] : 0.f;
    }
    if (tid < TM) { int n = n0 + tid; bs[tid] = (n < N) ? batch[n] : 0; }
    __syncthreads();

    int tx = tid & 7, ry = tid >> 3;      // cols: i*32+tx*4 (i=0..3,+q) rows: ry+16r
    u64 acc[4][8];
    #pragma unroll
    for (int r = 0; r < 4; ++r)
        #pragma unroll
        for (int p = 0; p < 8; ++p) acc[r][p] = 0ull;

    #pragma unroll 2
    for (int k4 = 0; k4 < IN0; k4 += 4) {
        float4 a4[4];
        #pragma unroll
        for (int r = 0; r < 4; ++r)
            a4[r] = *(const float4*)&as[(ry + 16 * r) * SA + k4];
        #pragma unroll
        for (int kk = 0; kk < 4; ++kk) {
            const float* wr = &wt[(k4 + kk) * F + tx * 4];
            ulonglong2 w0 = *(const ulonglong2*)(wr);
            ulonglong2 w1 = *(const ulonglong2*)(wr + 32);
            ulonglong2 w2 = *(const ulonglong2*)(wr + 64);
            ulonglong2 w3 = *(const ulonglong2*)(wr + 96);
            #pragma unroll
            for (int r = 0; r < 4; ++r) {
                float av = kk == 0 ? a4[r].x : kk == 1 ? a4[r].y : kk == 2 ? a4[r].z : a4[r].w;
                u64 aa = pk2(av);
                fma2(acc[r][0], aa, w0.x); fma2(acc[r][1], aa, w0.y);
                fma2(acc[r][2], aa, w1.x); fma2(acc[r][3], aa, w1.y);
                fma2(acc[r][4], aa, w2.x); fma2(acc[r][5], aa, w2.y);
                fma2(acc[r][6], aa, w3.x); fma2(acc[r][7], aa, w3.y);
            }
        }
    }

    float4 bias[4];
    #pragma unroll
    for (int i = 0; i < 4; ++i) bias[i] = *(const float4*)&g1b[i * 32 + tx * 4];
    #pragma unroll
    for (int r = 0; r < 4; ++r) {
        int row = ry + 16 * r;
        int n = n0 + row;
        if (n < N) {
            int g = bs[row];
            #pragma unroll
            for (int i = 0; i < 4; ++i) {
                int c = i * 32 + tx * 4;
                float4 l = *(const float4*)&d_lam1[g * F + c];
                float o0, o1, o2, o3;
                upk(acc[r][2 * i], o0, o1);
                upk(acc[r][2 * i + 1], o2, o3);
                float4 o;
                o.x = fmaxf(o0 + bias[i].x - l.x, 0.f);
                o.y = fmaxf(o1 + bias[i].y - l.y, 0.f);
                o.z = fmaxf(o2 + bias[i].z - l.z, 0.f);
                o.w = fmaxf(o3 + bias[i].w - l.w, 0.f);
                *(float4*)&d_hbuf[(size_t)n * F + c] = o;
            }
        }
    }
}

// ---------------- K4: hm = segment_mean(h) -----------------------------------
__global__ void k_hm() {
    int g = blockIdx.x, j = threadIdx.x;
    int s = d_off[g], e = d_off[g + 1];
    float a0 = 0.f, a1 = 0.f, a2 = 0.f, a3 = 0.f;
    const float* p = d_hbuf + j;
    int n = s;
    for (; n + 3 < e; n += 4) {
        a0 += p[(size_t)n * F];       a1 += p[(size_t)(n + 1) * F];
        a2 += p[(size_t)(n + 2) * F]; a3 += p[(size_t)(n + 3) * F];
    }
    for (; n < e; ++n) a0 += p[(size_t)n * F];
    d_hm[g * F + j] = (a0 + a1 + a2 + a3) / fmaxf((float)(e - s), 1.f);
}

// ---------------- K5: lam2 = hm @ l2w^T --------------------------------------
__global__ void k_lam2(const float* __restrict__ l2w) {
    __shared__ float mr[F];
    int g = blockIdx.x, j = threadIdx.x;
    mr[j] = d_hm[g * F + j];
    __syncthreads();
    float acc = 0.f;
    const float* w = l2w + j * F;
    #pragma unroll 4
    for (int k = 0; k < F; ++k) acc += mr[k] * w[k];
    d_lam2[g * F + j] = acc;
}

// ---------------- Kz: zero BN accumulators -----------------------------------
__global__ void k_zero() { d_S[threadIdx.x] = 0.f; }

// ---------------- K6: y = h @ g2w^T + g2b - lam2[batch]; BN partials ---------
__global__ __launch_bounds__(128, 2) void k_gemm2(
        const int* __restrict__ batch,
        const float* __restrict__ g2w, const float* __restrict__ g2b,
        int N, float* __restrict__ y) {
    extern __shared__ float sm[];
    float* wt   = sm;                    // [F][F]
    float* as   = sm + F * F;            // [TM][SB]
    float* red1 = as + TM * SB;          // [4][F]
    float* red2 = red1 + 4 * F;          // [4][F]
    int*   bs   = (int*)(red2 + 4 * F);
    int tid = threadIdx.x;
    int wid = tid >> 5, lane = tid & 31;
    int n0 = blockIdx.x * TM;

    for (int idx = tid; idx < F * F; idx += 128) {
        int k = idx >> 7, j = idx & 127;
        wt[idx] = g2w[j * F + k];
    }
    for (int idx = tid; idx < TM * 32; idx += 128) {
        int r = idx >> 5, c4 = idx & 31;
        int n = n0 + r;
        float4 v = (n < N) ? *(const float4*)&d_hbuf[(size_t)n * F + c4 * 4]
                           : make_float4(0.f, 0.f, 0.f, 0.f);
        *(float4*)&as[r * SB + c4 * 4] = v;
    }
    if (tid < TM) { int n = n0 + tid; bs[tid] = (n < N) ? batch[n] : 0; }
    __syncthreads();

    int tx = tid & 7, ry = tid >> 3;
    u64 acc[4][8];
    #pragma unroll
    for (int r = 0; r < 4; ++r)
        #pragma unroll
        for (int p = 0; p < 8; ++p) acc[r][p] = 0ull;

    #pragma unroll 2
    for (int k4 = 0; k4 < F; k4 += 4) {
        float4 a4[4];
        #pragma unroll
        for (int r = 0; r < 4; ++r)
            a4[r] = *(const float4*)&as[(ry + 16 * r) * SB + k4];
        #pragma unroll
        for (int kk = 0; kk < 4; ++kk) {
            const float* wr = &wt[(k4 + kk) * F + tx * 4];
            ulonglong2 w0 = *(const ulonglong2*)(wr);
            ulonglong2 w1 = *(const ulonglong2*)(wr + 32);
            ulonglong2 w2 = *(const ulonglong2*)(wr + 64);
            ulonglong2 w3 = *(const ulonglong2*)(wr + 96);
            #pragma unroll
            for (int r = 0; r < 4; ++r) {
                float av = kk == 0 ? a4[r].x : kk == 1 ? a4[r].y : kk == 2 ? a4[r].z : a4[r].w;
                u64 aa = pk2(av);
                fma2(acc[r][0], aa, w0.x); fma2(acc[r][1], aa, w0.y);
                fma2(acc[r][2], aa, w1.x); fma2(acc[r][3], aa, w1.y);
                fma2(acc[r][4], aa, w2.x); fma2(acc[r][5], aa, w2.y);
                fma2(acc[r][6], aa, w3.x); fma2(acc[r][7], aa, w3.y);
            }
        }
    }

    float4 bias[4];
    #pragma unroll
    for (int i = 0; i < 4; ++i) bias[i] = *(const float4*)&g2b[i * 32 + tx * 4];

    float s1[16], s2[16];
    #pragma unroll
    for (int c = 0; c < 16; ++c) { s1[c] = 0.f; s2[c] = 0.f; }

    #pragma unroll
    for (int r = 0; r < 4; ++r) {
        int row = ry + 16 * r;
        int n = n0 + row;
        if (n < N) {
            int g = bs[row];
            #pragma unroll
            for (int i = 0; i < 4; ++i) {
                int c = i * 32 + tx * 4;
                float4 l = *(const float4*)&d_lam2[g * F + c];
                float o0, o1, o2, o3;
                upk(acc[r][2 * i], o0, o1);
                upk(acc[r][2 * i + 1], o2, o3);
                float4 o;
                o.x = o0 + bias[i].x - l.x;
                o.y = o1 + bias[i].y - l.y;
                o.z = o2 + bias[i].z - l.z;
                o.w = o3 + bias[i].w - l.w;
                *(float4*)&y[(size_t)n * F + c] = o;
                s1[i * 4 + 0] += o.x; s2[i * 4 + 0] += o.x * o.x;
                s1[i * 4 + 1] += o.y; s2[i * 4 + 1] += o.y * o.y;
                s1[i * 4 + 2] += o.z; s2[i * 4 + 2] += o.z * o.z;
                s1[i * 4 + 3] += o.w; s2[i * 4 + 3] += o.w * o.w;
            }
        }
    }
    // reduce across the 4 ry values inside each warp (lane bits 3,4)
    #pragma unroll
    for (int c = 0; c < 16; ++c) {
        s1[c] += __shfl_xor_sync(0xffffffffu, s1[c], 8);
        s1[c] += __shfl_xor_sync(0xffffffffu, s1[c], 16);
        s2[c] += __shfl_xor_sync(0xffffffffu, s2[c], 8);
        s2[c] += __shfl_xor_sync(0xffffffffu, s2[c], 16);
    }
    if (lane < 8) {
        #pragma unroll
        for (int i = 0; i < 4; ++i) {
            int c = i * 32 + tx * 4;
            #pragma unroll
            for (int q = 0; q < 4; ++q) {
                red1[wid * F + c + q] = s1[i * 4 + q];
                red2[wid * F + c + q] = s2[i * 4 + q];
            }
        }
    }
    __syncthreads();
    if (tid < F) {
        float a = 0.f, b = 0.f;
        #pragma unroll
        for (int w = 0; w < 4; ++w) { a += red1[w * F + tid]; b += red2[w * F + tid]; }
        atomicAdd(&d_S[tid], a);
        atomicAdd(&d_S[F + tid], b);
    }
}

// ---------------- K7: BN finalize --------------------------------------------
__global__ void k_bnfin(const float* __restrict__ bn_g, const float* __restrict__ bn_b, int N) {
    int j = threadIdx.x;
    float invN = 1.f / (float)N;
    float mu  = d_S[j] * invN;
    float var = d_S[F + j] * invN - mu * mu;
    float sc  = bn_g[j] * rsqrtf(var + EPS);
    d_scale[j] = sc;
    d_shift[j] = bn_b[j] - mu * sc;
}

// ---------------- K8: out = x + y*scale + shift ------------------------------
__global__ void k_final(const float* __restrict__ x, float* __restrict__ out, int total4) {
    int i = blockIdx.x * blockDim.x + threadIdx.x;
    if (i >= total4) return;
    int c4 = i & 31;
    float4 y  = ((float4*)out)[i];
    float4 xv = ((const float4*)x)[i];
    float4 sc = ((const float4*)d_scale)[c4];
    float4 sh = ((const float4*)d_shift)[c4];
    y.x = xv.x + y.x * sc.x + sh.x;
    y.y = xv.y + y.y * sc.y + sh.y;
    y.z = xv.z + y.z * sc.z + sh.z;
    y.w = xv.w + y.w * sc.w + sh.w;
    ((float4*)out)[i] = y;
}

// ---------------- launch -----------------------------------------------------
extern "C" void kernel_launch(void* const* d_in, const int* in_sizes, int n_in,
                              void* d_out, int out_size) {
    const float* x    = (const float*)d_in[0];
    const int*   batch= (const int*)  d_in[1];
    const float* pers = (const float*)d_in[2];
    const float* g1w  = (const float*)d_in[3];
    const float* g1b  = (const float*)d_in[4];
    const float* l1w  = (const float*)d_in[5];
    const float* g2w  = (const float*)d_in[6];
    const float* g2b  = (const float*)d_in[7];
    const float* l2w  = (const float*)d_in[8];
    const float* bn_g = (const float*)d_in[9];
    const float* bn_b = (const float*)d_in[10];
    float* out = (float*)d_out;

    int N = in_sizes[1];
    int NB = (N + TM - 1) / TM;

    const int SMEM1 = (IN0 * F + TM * SA) * 4 + TM * 4;
    const int SMEM2 = (F * F + TM * SB + 8 * F) * 4 + TM * 4;
    cudaFuncSetAttribute(k_gemm1, cudaFuncAttributeMaxDynamicSharedMemorySize, SMEM1);
    cudaFuncSetAttribute(k_gemm2, cudaFuncAttributeMaxDynamicSharedMemorySize, SMEM2);

    k_off <<<(G + 1 + 255) / 256, 256>>>(batch, N);
    k_xm  <<<G, 160>>>(x, pers, N);
    k_lam1<<<G, 128>>>(l1w);
    k_gemm1<<<NB, 128, SMEM1>>>(x, pers, batch, g1w, g1b, N);
    k_hm  <<<G, 128>>>();
    k_lam2<<<G, 128>>>(l2w);
    k_zero<<<1, 2 * F>>>();
    k_gemm2<<<NB, 128, SMEM2>>>(batch, g2w, g2b, N, out);
    k_bnfin<<<1, F>>>(bn_g, bn_b, N);
    int total4 = N * (F / 4);
    k_final<<<(total4 + 255) / 256, 256>>>(x, out, total4);
}

// round 8
// speedup vs baseline: 1.2915x; 1.2915x over previous
#include <cuda_runtime.h>
#include <cuda_bf16.h>
#include <math.h>
#include <stdint.h>

#define G 2048
#define F 128
#define IN0 144
#define EPS 1e-5f
#define BM 128

#define SA1 152   // elems per row, gemm1 tiles (K=144 + pad) ; 76 words
#define SA2 136   // elems per row, gemm2 tiles (K=128 + pad) ; 68 words

typedef unsigned int u32;

// ---------------- scratch ----------------------------------------------------
__device__ __align__(16) float d_hbuf[500000 * 128];
__device__ int   d_off[G + 1];
__device__ __align__(16) float d_xm[G * IN0];
__device__ __align__(16) float d_lam1[G * F];
__device__ __align__(16) float d_hm[G * F];
__device__ __align__(16) float d_lam2[G * F];
__device__ __align__(16) float d_S[2 * F];
__device__ __align__(16) float d_scale[F];
__device__ __align__(16) float d_shift[F];

// ---------------- helpers ----------------------------------------------------
__device__ __forceinline__ u32 pkbf(float a, float b) {
    __nv_bfloat16 x = __float2bfloat16(a), y = __float2bfloat16(b);
    unsigned short ux = *(unsigned short*)&x, uy = *(unsigned short*)&y;
    return (u32)ux | ((u32)uy << 16);
}
__device__ __forceinline__ void splitf(float v, float& hi, float& lo) {
    __nv_bfloat16 h = __float2bfloat16(v);
    hi = __bfloat162float(h);
    lo = v - hi;
}
__device__ __forceinline__ void mma16816(float* c, u32 a0, u32 a1, u32 a2, u32 a3,
                                         u32 b0, u32 b1) {
    asm volatile("mma.sync.aligned.m16n8k16.row.col.f32.bf16.bf16.f32 "
                 "{%0,%1,%2,%3},{%4,%5,%6,%7},{%8,%9},{%0,%1,%2,%3};"
                 : "+f"(c[0]), "+f"(c[1]), "+f"(c[2]), "+f"(c[3])
                 : "r"(a0), "r"(a1), "r"(a2), "r"(a3), "r"(b0), "r"(b1));
}

// ---------------- K0: graph offsets ------------------------------------------
__global__ void k_off(const int* __restrict__ batch, int N) {
    int g = blockIdx.x * blockDim.x + threadIdx.x;
    if (g > G) return;
    int lo = 0, hi = N;
    while (lo < hi) { int mid = (lo + hi) >> 1; if (batch[mid] < g) lo = mid + 1; else hi = mid; }
    d_off[g] = lo;
}

// ---------------- K1: xm = segment_mean(x0) ----------------------------------
__global__ void k_xm(const float* __restrict__ x, const float* __restrict__ pers, int N) {
    int g = blockIdx.x;
    int j = threadIdx.x;
    if (j >= IN0) return;
    int s = d_off[g], e = d_off[g + 1];
    float a0 = 0.f, a1 = 0.f, a2 = 0.f, a3 = 0.f;
    if (j < F) {
        const float* p = x + j;
        int n = s;
        for (; n + 3 < e; n += 4) {
            a0 += p[(size_t)n * F];       a1 += p[(size_t)(n + 1) * F];
            a2 += p[(size_t)(n + 2) * F]; a3 += p[(size_t)(n + 3) * F];
        }
        for (; n < e; ++n) a0 += p[(size_t)n * F];
    } else {
        int jj = j - F; int pp = jj >> 1; int c = jj & 1;
        const float* p = pers + (size_t)pp * N * 2 + c;
        int n = s;
        for (; n + 3 < e; n += 4) {
            a0 += p[(size_t)n * 2];       a1 += p[(size_t)(n + 1) * 2];
            a2 += p[(size_t)(n + 2) * 2]; a3 += p[(size_t)(n + 3) * 2];
        }
        for (; n < e; ++n) a0 += p[(size_t)n * 2];
    }
    d_xm[g * IN0 + j] = (a0 + a1 + a2 + a3) / fmaxf((float)(e - s), 1.f);
}

// ---------------- K2: lam1 = xm @ l1w^T --------------------------------------
__global__ void k_lam1(const float* __restrict__ l1w) {
    __shared__ float mr[IN0];
    int g = blockIdx.x, j = threadIdx.x;
    for (int k = j; k < IN0; k += 128) mr[k] = d_xm[g * IN0 + k];
    __syncthreads();
    float acc = 0.f;
    const float* w = l1w + j * IN0;
    #pragma unroll 4
    for (int k = 0; k < IN0; ++k) acc += mr[k] * w[k];
    d_lam1[g * F + j] = acc;
}

// ---------------- K3: gemm1 via mma.sync bf16 (3-term split) -----------------
// smem elems (bf16): AHI[128*SA1] ALO BHI[128*SA1] BLO, then bs[128] ints
#define G1_E  (128 * SA1)
#define G1_SMEM (4 * G1_E * 2 + 128 * 4)

__global__ __launch_bounds__(256, 1) void k_gemm1(
        const float* __restrict__ x, const float* __restrict__ pers,
        const int* __restrict__ batch,
        const float* __restrict__ g1w, const float* __restrict__ g1b, int N) {
    extern __shared__ __align__(16) unsigned short smem_us[];
    unsigned short* AHI = smem_us;
    unsigned short* ALO = smem_us + G1_E;
    unsigned short* BHI = smem_us + 2 * G1_E;
    unsigned short* BLO = smem_us + 3 * G1_E;
    int* bs = (int*)(smem_us + 4 * G1_E);
    int tid = threadIdx.x, lane = tid & 31, wid = tid >> 5;
    int n0 = blockIdx.x * BM;

    // stage A = [x | pers] split hi/lo
    for (int idx = tid; idx < BM * 72; idx += 256) {
        int r = idx / 72, pr = idx % 72;
        int n = n0 + r;
        float2 v = make_float2(0.f, 0.f);
        if (n < N) {
            if (pr < 64) v = *(const float2*)&x[(size_t)n * F + pr * 2];
            else { int p = pr - 64; v = *(const float2*)&pers[((size_t)p * N + n) * 2]; }
        }
        float h0, l0, h1, l1;
        splitf(v.x, h0, l0); splitf(v.y, h1, l1);
        int o = r * SA1 + 2 * pr;
        *(u32*)&AHI[o] = pkbf(h0, h1);
        *(u32*)&ALO[o] = pkbf(l0, l1);
    }
    // stage B = g1w [128][144] split hi/lo
    for (int idx = tid; idx < F * 72; idx += 256) {
        int r = idx / 72, pr = idx % 72;
        float2 v = *(const float2*)&g1w[r * IN0 + pr * 2];
        float h0, l0, h1, l1;
        splitf(v.x, h0, l0); splitf(v.y, h1, l1);
        int o = r * SA1 + 2 * pr;
        *(u32*)&BHI[o] = pkbf(h0, h1);
        *(u32*)&BLO[o] = pkbf(l0, l1);
    }
    if (tid < BM) { int n = n0 + tid; bs[tid] = (n < N) ? batch[n] : 0; }
    __syncthreads();

    int wm = wid & 1, wn = wid >> 1;        // warp tile: rows wm*64.., cols wn*32..
    float acc[4][4][4];
    #pragma unroll
    for (int mt = 0; mt < 4; ++mt)
        #pragma unroll
        for (int nt = 0; nt < 4; ++nt)
            #pragma unroll
            for (int q = 0; q < 4; ++q) acc[mt][nt][q] = 0.f;

    const u32* Ah = (const u32*)AHI; const u32* Al = (const u32*)ALO;
    const u32* Bh = (const u32*)BHI; const u32* Bl = (const u32*)BLO;
    int rq = lane >> 2, kq = lane & 3;      // quad row / k-pair id

    for (int ks = 0; ks < 9; ++ks) {
        int ku = ks * 8 + kq;
        u32 bh[4][2], bl[4][2];
        #pragma unroll
        for (int nt = 0; nt < 4; ++nt) {
            int c = wn * 32 + nt * 8 + rq;
            int o = c * (SA1 / 2) + ku;
            bh[nt][0] = Bh[o]; bh[nt][1] = Bh[o + 4];
            bl[nt][0] = Bl[o]; bl[nt][1] = Bl[o + 4];
        }
        #pragma unroll
        for (int mt = 0; mt < 4; ++mt) {
            int r = wm * 64 + mt * 16 + rq;
            int o0 = r * (SA1 / 2) + ku, o1 = (r + 8) * (SA1 / 2) + ku;
            u32 ah0 = Ah[o0], ah1 = Ah[o1], ah2 = Ah[o0 + 4], ah3 = Ah[o1 + 4];
            u32 al0 = Al[o0], al1 = Al[o1], al2 = Al[o0 + 4], al3 = Al[o1 + 4];
            #pragma unroll
            for (int nt = 0; nt < 4; ++nt) {
                mma16816(acc[mt][nt], ah0, ah1, ah2, ah3, bh[nt][0], bh[nt][1]);
                mma16816(acc[mt][nt], ah0, ah1, ah2, ah3, bl[nt][0], bl[nt][1]);
                mma16816(acc[mt][nt], al0, al1, al2, al3, bh[nt][0], bh[nt][1]);
            }
        }
    }

    // epilogue: o = relu(acc + g1b[c] - lam1[g][c]) -> d_hbuf
    #pragma unroll
    for (int mt = 0; mt < 4; ++mt) {
        int r0 = wm * 64 + mt * 16 + rq;
        #pragma unroll
        for (int half = 0; half < 2; ++half) {
            int r = r0 + half * 8;
            int n = n0 + r;
            if (n < N) {
                int g = bs[r];
                #pragma unroll
                for (int nt = 0; nt < 4; ++nt) {
                    int c = wn * 32 + nt * 8 + kq * 2;
                    float2 bi = *(const float2*)&g1b[c];
                    float2 lm = *(const float2*)&d_lam1[g * F + c];
                    float2 o;
                    o.x = fmaxf(acc[mt][nt][half * 2]     + bi.x - lm.x, 0.f);
                    o.y = fmaxf(acc[mt][nt][half * 2 + 1] + bi.y - lm.y, 0.f);
                    *(float2*)&d_hbuf[(size_t)n * F + c] = o;
                }
            }
        }
    }
}

// ---------------- K4: hm = segment_mean(h) -----------------------------------
__global__ void k_hm() {
    int g = blockIdx.x, j = threadIdx.x;
    int s = d_off[g], e = d_off[g + 1];
    float a0 = 0.f, a1 = 0.f, a2 = 0.f, a3 = 0.f;
    const float* p = d_hbuf + j;
    int n = s;
    for (; n + 3 < e; n += 4) {
        a0 += p[(size_t)n * F];       a1 += p[(size_t)(n + 1) * F];
        a2 += p[(size_t)(n + 2) * F]; a3 += p[(size_t)(n + 3) * F];
    }
    for (; n < e; ++n) a0 += p[(size_t)n * F];
    d_hm[g * F + j] = (a0 + a1 + a2 + a3) / fmaxf((float)(e - s), 1.f);
}

// ---------------- K5: lam2 = hm @ l2w^T --------------------------------------
__global__ void k_lam2(const float* __restrict__ l2w) {
    __shared__ float mr[F];
    int g = blockIdx.x, j = threadIdx.x;
    mr[j] = d_hm[g * F + j];
    __syncthreads();
    float acc = 0.f;
    const float* w = l2w + j * F;
    #pragma unroll 4
    for (int k = 0; k < F; ++k) acc += mr[k] * w[k];
    d_lam2[g * F + j] = acc;
}

// ---------------- Kz: zero BN accumulators -----------------------------------
__global__ void k_zero() { d_S[threadIdx.x] = 0.f; }

// ---------------- K6: gemm2 via mma.sync; y -> out; BN partials --------------
#define G2_E  (128 * SA2)
#define G2_SMEM (4 * G2_E * 2 + 128 * 4 + 256 * 4)

__global__ __launch_bounds__(256, 1) void k_gemm2(
        const int* __restrict__ batch,
        const float* __restrict__ g2w, const float* __restrict__ g2b,
        int N, float* __restrict__ y) {
    extern __shared__ __align__(16) unsigned short smem_us[];
    unsigned short* AHI = smem_us;
    unsigned short* ALO = smem_us + G2_E;
    unsigned short* BHI = smem_us + 2 * G2_E;
    unsigned short* BLO = smem_us + 3 * G2_E;
    int*   bs  = (int*)(smem_us + 4 * G2_E);
    float* sbn = (float*)(bs + 128);
    int tid = threadIdx.x, lane = tid & 31, wid = tid >> 5;
    int n0 = blockIdx.x * BM;

    if (tid < 256) sbn[tid] = 0.f;

    // stage A from d_hbuf (fp32 -> hi/lo)
    for (int idx = tid; idx < BM * 64; idx += 256) {
        int r = idx >> 6, pr = idx & 63;
        int n = n0 + r;
        float2 v = (n < N) ? *(const float2*)&d_hbuf[(size_t)n * F + pr * 2]
                           : make_float2(0.f, 0.f);
        float h0, l0, h1, l1;
        splitf(v.x, h0, l0); splitf(v.y, h1, l1);
        int o = r * SA2 + 2 * pr;
        *(u32*)&AHI[o] = pkbf(h0, h1);
        *(u32*)&ALO[o] = pkbf(l0, l1);
    }
    // stage B = g2w [128][128]
    for (int idx = tid; idx < F * 64; idx += 256) {
        int r = idx >> 6, pr = idx & 63;
        float2 v = *(const float2*)&g2w[r * F + pr * 2];
        float h0, l0, h1, l1;
        splitf(v.x, h0, l0); splitf(v.y, h1, l1);
        int o = r * SA2 + 2 * pr;
        *(u32*)&BHI[o] = pkbf(h0, h1);
        *(u32*)&BLO[o] = pkbf(l0, l1);
    }
    if (tid < BM) { int n = n0 + tid; bs[tid] = (n < N) ? batch[n] : 0; }
    __syncthreads();

    int wm = wid & 1, wn = wid >> 1;
    float acc[4][4][4];
    #pragma unroll
    for (int mt = 0; mt < 4; ++mt)
        #pragma unroll
        for (int nt = 0; nt < 4; ++nt)
            #pragma unroll
            for (int q = 0; q < 4; ++q) acc[mt][nt][q] = 0.f;

    const u32* Ah = (const u32*)AHI; const u32* Al = (const u32*)ALO;
    const u32* Bh = (const u32*)BHI; const u32* Bl = (const u32*)BLO;
    int rq = lane >> 2, kq = lane & 3;

    for (int ks = 0; ks < 8; ++ks) {
        int ku = ks * 8 + kq;
        u32 bh[4][2], bl[4][2];
        #pragma unroll
        for (int nt = 0; nt < 4; ++nt) {
            int c = wn * 32 + nt * 8 + rq;
            int o = c * (SA2 / 2) + ku;
            bh[nt][0] = Bh[o]; bh[nt][1] = Bh[o + 4];
            bl[nt][0] = Bl[o]; bl[nt][1] = Bl[o + 4];
        }
        #pragma unroll
        for (int mt = 0; mt < 4; ++mt) {
            int r = wm * 64 + mt * 16 + rq;
            int o0 = r * (SA2 / 2) + ku, o1 = (r + 8) * (SA2 / 2) + ku;
            u32 ah0 = Ah[o0], ah1 = Ah[o1], ah2 = Ah[o0 + 4], ah3 = Ah[o1 + 4];
            u32 al0 = Al[o0], al1 = Al[o1], al2 = Al[o0 + 4], al3 = Al[o1 + 4];
            #pragma unroll
            for (int nt = 0; nt < 4; ++nt) {
                mma16816(acc[mt][nt], ah0, ah1, ah2, ah3, bh[nt][0], bh[nt][1]);
                mma16816(acc[mt][nt], ah0, ah1, ah2, ah3, bl[nt][0], bl[nt][1]);
                mma16816(acc[mt][nt], al0, al1, al2, al3, bh[nt][0], bh[nt][1]);
            }
        }
    }

    float s1[4][2], s2[4][2];
    #pragma unroll
    for (int nt = 0; nt < 4; ++nt)
        { s1[nt][0] = s1[nt][1] = 0.f; s2[nt][0] = s2[nt][1] = 0.f; }

    #pragma unroll
    for (int mt = 0; mt < 4; ++mt) {
        int r0 = wm * 64 + mt * 16 + rq;
        #pragma unroll
        for (int half = 0; half < 2; ++half) {
            int r = r0 + half * 8;
            int n = n0 + r;
            if (n < N) {
                int g = bs[r];
                #pragma unroll
                for (int nt = 0; nt < 4; ++nt) {
                    int c = wn * 32 + nt * 8 + kq * 2;
                    float2 bi = *(const float2*)&g2b[c];
                    float2 lm = *(const float2*)&d_lam2[g * F + c];
                    float2 o;
                    o.x = acc[mt][nt][half * 2]     + bi.x - lm.x;
                    o.y = acc[mt][nt][half * 2 + 1] + bi.y - lm.y;
                    *(float2*)&y[(size_t)n * F + c] = o;
                    s1[nt][0] += o.x; s2[nt][0] += o.x * o.x;
                    s1[nt][1] += o.y; s2[nt][1] += o.y * o.y;
                }
            }
        }
    }
    // reduce across rq (lane>>2) within warp
    #pragma unroll
    for (int nt = 0; nt < 4; ++nt)
        #pragma unroll
        for (int q = 0; q < 2; ++q) {
            s1[nt][q] += __shfl_xor_sync(0xffffffffu, s1[nt][q], 4);
            s1[nt][q] += __shfl_xor_sync(0xffffffffu, s1[nt][q], 8);
            s1[nt][q] += __shfl_xor_sync(0xffffffffu, s1[nt][q], 16);
            s2[nt][q] += __shfl_xor_sync(0xffffffffu, s2[nt][q], 4);
            s2[nt][q] += __shfl_xor_sync(0xffffffffu, s2[nt][q], 8);
            s2[nt][q] += __shfl_xor_sync(0xffffffffu, s2[nt][q], 16);
        }
    if (lane < 4) {
        #pragma unroll
        for (int nt = 0; nt < 4; ++nt) {
            int c = wn * 32 + nt * 8 + lane * 2;
            atomicAdd(&sbn[c],         s1[nt][0]);
            atomicAdd(&sbn[c + 1],     s1[nt][1]);
            atomicAdd(&sbn[F + c],     s2[nt][0]);
            atomicAdd(&sbn[F + c + 1], s2[nt][1]);
        }
    }
    __syncthreads();
    if (tid < 256) atomicAdd(&d_S[tid], sbn[tid]);
}

// ---------------- K7: BN finalize --------------------------------------------
__global__ void k_bnfin(const float* __restrict__ bn_g, const float* __restrict__ bn_b, int N) {
    int j = threadIdx.x;
    float invN = 1.f / (float)N;
    float mu  = d_S[j] * invN;
    float var = d_S[F + j] * invN - mu * mu;
    float sc  = bn_g[j] * rsqrtf(var + EPS);
    d_scale[j] = sc;
    d_shift[j] = bn_b[j] - mu * sc;
}

// ---------------- K8: out = x + y*scale + shift ------------------------------
__global__ void k_final(const float* __restrict__ x, float* __restrict__ out, int total4) {
    int i = blockIdx.x * blockDim.x + threadIdx.x;
    if (i >= total4) return;
    int c4 = i & 31;
    float4 yv = ((float4*)out)[i];
    float4 xv = ((const float4*)x)[i];
    float4 sc = ((const float4*)d_scale)[c4];
    float4 sh = ((const float4*)d_shift)[c4];
    yv.x = xv.x + yv.x * sc.x + sh.x;
    yv.y = xv.y + yv.y * sc.y + sh.y;
    yv.z = xv.z + yv.z * sc.z + sh.z;
    yv.w = xv.w + yv.w * sc.w + sh.w;
    ((float4*)out)[i] = yv;
}

// ---------------- launch -----------------------------------------------------
extern "C" void kernel_launch(void* const* d_in, const int* in_sizes, int n_in,
                              void* d_out, int out_size) {
    const float* x    = (const float*)d_in[0];
    const int*   batch= (const int*)  d_in[1];
    const float* pers = (const float*)d_in[2];
    const float* g1w  = (const float*)d_in[3];
    const float* g1b  = (const float*)d_in[4];
    const float* l1w  = (const float*)d_in[5];
    const float* g2w  = (const float*)d_in[6];
    const float* g2b  = (const float*)d_in[7];
    const float* l2w  = (const float*)d_in[8];
    const float* bn_g = (const float*)d_in[9];
    const float* bn_b = (const float*)d_in[10];
    float* out = (float*)d_out;

    int N = in_sizes[1];
    int NB = (N + BM - 1) / BM;

    cudaFuncSetAttribute(k_gemm1, cudaFuncAttributeMaxDynamicSharedMemorySize, G1_SMEM);
    cudaFuncSetAttribute(k_gemm2, cudaFuncAttributeMaxDynamicSharedMemorySize, G2_SMEM);

    k_off <<<(G + 1 + 255) / 256, 256>>>(batch, N);
    k_xm  <<<G, 160>>>(x, pers, N);
    k_lam1<<<G, 128>>>(l1w);
    k_gemm1<<<NB, 256, G1_SMEM>>>(x, pers, batch, g1w, g1b, N);
    k_hm  <<<G, 128>>>();
    k_lam2<<<G, 128>>>(l2w);
    k_zero<<<1, 2 * F>>>();
    k_gemm2<<<NB, 256, G2_SMEM>>>(batch, g2w, g2b, N, out);
    k_bnfin<<<1, F>>>(bn_g, bn_b, N);
    int total4 = N * (F / 4);
    k_final<<<(total4 + 255) / 256, 256>>>(x, out, total4);
}